// round 16
// baseline (speedup 1.0000x reference)
#include <cuda_runtime.h>
#include <cuda_fp16.h>
#include <math.h>
#include <stdint.h>

#define NMAX  100000
#define EMAX  1600000
#define FIN   512
#define H1    8
#define D1    64      // H1 * C1
#define NCLS  40
#define SLOPE 0.2f
#define SCAN_B 1024
#define LOG2E 1.4426950408889634f

// dynamic smem for gemm1 part: As[3][128][20] then Bs[3][16][72] (3-stage pipeline)
#define AS_STRIDE 20
#define BS_STRIDE 72
#define AS_BUF (128 * AS_STRIDE)             // 2560 floats per stage
#define BS_BUF (16 * BS_STRIDE)              // 1152 floats per stage
#define GEMM1_SMEM_FLOATS (3 * AS_BUF + 3 * BS_BUF)   // 11136 floats = 44544 B
#define AS_OFF 0
#define BS_OFF (3 * AS_BUF)

// ---------------- scratch (static device globals; no allocations) ----------
__device__ __align__(256) int    g_csr [EMAX];      // src ids grouped by dst
__device__ __align__(256) int    g_deg [NMAX];      // zero-init; re-zeroed by k_scan each run
__device__ __align__(256) int    g_row [NMAX + 1];  // CSR row pointers
__device__ __align__(256) int    g_cur [NMAX];
__device__ __align__(256) volatile long long g_bsum64[SCAN_B];  // flagged block sums
__device__ __align__(256) __half g_h1h [NMAX * D1];    // h1 in fp16 (gathered)
__device__ __align__(256) float  g_as1 [NMAX * H1];    // logits pre-scaled by log2(e)
__device__ __align__(256) float  g_ad1 [NMAX * H1];
__device__ __align__(256) __half g_hacth[NMAX * D1];   // hact in fp16
__device__ __align__(256) __half g_h2h [NMAX * NCLS];  // h2 in fp16 (gathered); row = 5 uint4
__device__ __align__(256) float  g_as2 [NMAX];         // pre-scaled by log2(e)
__device__ __align__(256) float  g_ad2 [NMAX];

// branch-free leaky-relu (slope>0): max(t, 0.2t)
__device__ __forceinline__ float lrelu(float v) { return fmaxf(v, SLOPE * v); }

// per-block int64-vs-int32 detection
__device__ __forceinline__ int detect_is64_block(const int* ei) {
    __shared__ int s_is64;
    if (threadIdx.x == 0) {
        int nz = 0;
#pragma unroll
        for (int k = 1; k < 32; k += 2) nz |= ei[k];
        s_is64 = (nz == 0);
    }
    __syncthreads();
    return s_is64;
}

// ---------------- single-kernel exclusive scan (all blocks co-resident) -----
__global__ void k_scan(int n, int E) {
    __shared__ int sh[SCAN_B];
    __shared__ int s_off;
    const int tid = threadIdx.x, bid = blockIdx.x;
    const int i = bid * SCAN_B + tid;
    int v = (i < n) ? g_deg[i] : 0;
    if (i < n) g_deg[i] = 0;                 // restore state for next replay
    sh[tid] = v;
    __syncthreads();
#pragma unroll
    for (int off = 1; off < SCAN_B; off <<= 1) {
        int t = (tid >= off) ? sh[tid - off] : 0;
        __syncthreads();
        sh[tid] += t;
        __syncthreads();
    }
    int incl = sh[tid];
    if (tid == SCAN_B - 1)
        g_bsum64[bid] = (1LL << 32) | (unsigned)incl;
    if (tid < 32) {
        int sum = 0;
        for (int p = tid; p < bid; p += 32) {
            long long w;
            do { w = g_bsum64[p]; } while ((int)(w >> 32) == 0);
            sum += (int)w;
        }
#pragma unroll
        for (int o = 16; o > 0; o >>= 1) sum += __shfl_xor_sync(0xFFFFFFFFu, sum, o);
        if (tid == 0) s_off = sum;
    }
    __syncthreads();
    if (i < n) {
        int r = s_off + incl - v;
        g_row[i] = r;
        g_cur[i] = r;
    }
    if (i == n - 1) g_row[n] = E;
}

// ---------------- standalone scatter (block 0 also resets scan flags) -------
__global__ void k_scatter(const void* __restrict__ ei, int E) {
    if (blockIdx.x == 0)
        for (int k = threadIdx.x; k < SCAN_B; k += 256)
            g_bsum64[k] = 0;
    int is64 = detect_is64_block((const int*)ei);
    int i = blockIdx.x * 256 + threadIdx.x;
    if (i >= E) return;
    int s, d;
    if (is64) {
        const long long* p = (const long long*)ei;
        s = (int)p[i];
        d = (int)p[(long long)E + i];
    } else {
        const int* p = (const int*)ei;
        s = p[i];
        d = p[E + i];
    }
    int pos = atomicAdd(&g_cur[d], 1);
    g_csr[pos] = s;
}

// ---------------- fused: GEMM1 (TF32 mma, 3-stage cp.async) + histogram -----
// blocks [0, gemmBlocks): GEMM1 h1 = x @ W1 with fused attention logits
// blocks [gemmBlocks, ...): degree histogram (independent of GEMM — overlaps)
__global__ __launch_bounds__(256, 3)
void k_gemm1_build(const float* __restrict__ x, const float* __restrict__ W,
                   const float* __restrict__ attS, const float* __restrict__ attD,
                   const void* __restrict__ ei, int n, int E, int gemmBlocks) {
    if ((int)blockIdx.x >= gemmBlocks) {
        // ------- histogram part -------
        int b = blockIdx.x - gemmBlocks;
        int is64 = detect_is64_block((const int*)ei);
        int i = b * 256 + threadIdx.x;
        if (i >= E) return;
        int d;
        if (is64) d = (int)((const long long*)ei)[(long long)E + i];
        else      d = ((const int*)ei)[E + i];
        atomicAdd(&g_deg[d], 1);
        return;
    }

    // ------- GEMM part: block tile M=128 N=64, K staged 16; 8 warps 4x2 -----
    extern __shared__ float sm[];
    float* Asm = sm + AS_OFF;                       // [3][128][20]
    float* Bsm = sm + BS_OFF;                       // [3][16][72]
    const int t    = threadIdx.x;
    const int warp = t >> 5, lane = t & 31;
    const int g    = lane >> 2, tg = lane & 3;
    const int wm   = warp >> 1, wn = warp & 1;
    const int m0   = wm * 32, n0 = wn * 32;
    const int row0 = blockIdx.x * 128;

    float c[2][4][4];
#pragma unroll
    for (int mi = 0; mi < 2; mi++)
#pragma unroll
        for (int nj = 0; nj < 4; nj++)
#pragma unroll
            for (int q = 0; q < 4; q++) c[mi][nj][q] = 0.f;

    auto load_stage = [&](int stage, int buf) {
        const int k0 = stage * 16;
        float* Ab = Asm + buf * AS_BUF;
        float* Bb = Bsm + buf * BS_BUF;
#pragma unroll
        for (int p = 0; p < 2; p++) {              // A: 128x16 = 512 float4
            int idx = t + p * 256;
            int r = idx >> 2, c4 = idx & 3;
            const float* src = x + (size_t)(row0 + r) * FIN + k0 + c4 * 4;
            uint32_t daddr = (uint32_t)__cvta_generic_to_shared(Ab + r * AS_STRIDE + c4 * 4);
            int sb = (row0 + r < n) ? 16 : 0;
            asm volatile("cp.async.cg.shared.global [%0], [%1], 16, %2;\n"
                         :: "r"(daddr), "l"(src), "r"(sb));
        }
        {                                          // B: 16x64 = 256 float4
            int kk = t >> 4, n4 = t & 15;
            const float* src = W + (size_t)(k0 + kk) * D1 + n4 * 4;
            uint32_t daddr = (uint32_t)__cvta_generic_to_shared(Bb + kk * BS_STRIDE + n4 * 4);
            asm volatile("cp.async.cg.shared.global [%0], [%1], 16;\n"
                         :: "r"(daddr), "l"(src));
        }
    };

    const int NSTAGE = FIN / 16;   // 32
    load_stage(0, 0);
    asm volatile("cp.async.commit_group;\n");
    load_stage(1, 1);
    asm volatile("cp.async.commit_group;\n");

    for (int it = 0; it < NSTAGE; it++) {
        asm volatile("cp.async.wait_group 1;\n");  // stage it landed (it+1 may fly)
        __syncthreads();                            // publish + protect buf (it+2)%3
        if (it + 2 < NSTAGE) {
            load_stage(it + 2, (it + 2) % 3);
            asm volatile("cp.async.commit_group;\n");
        }
        const int buf = it % 3;
        const float* Ab = Asm + buf * AS_BUF;
        const float* Bb = Bsm + buf * BS_BUF;
#pragma unroll
        for (int ks = 0; ks < 2; ks++) {
            const int kb = ks * 8;
            uint32_t a[2][4], b[4][2];
#pragma unroll
            for (int mi = 0; mi < 2; mi++) {
                const int mr = m0 + mi * 16;
                a[mi][0] = __float_as_uint(Ab[(mr + g    ) * AS_STRIDE + kb + tg    ]);
                a[mi][1] = __float_as_uint(Ab[(mr + g + 8) * AS_STRIDE + kb + tg    ]);
                a[mi][2] = __float_as_uint(Ab[(mr + g    ) * AS_STRIDE + kb + tg + 4]);
                a[mi][3] = __float_as_uint(Ab[(mr + g + 8) * AS_STRIDE + kb + tg + 4]);
            }
#pragma unroll
            for (int nj = 0; nj < 4; nj++) {
                const int nc = n0 + nj * 8;
                b[nj][0] = __float_as_uint(Bb[(kb + tg    ) * BS_STRIDE + nc + g]);
                b[nj][1] = __float_as_uint(Bb[(kb + tg + 4) * BS_STRIDE + nc + g]);
            }
#pragma unroll
            for (int mi = 0; mi < 2; mi++)
#pragma unroll
                for (int nj = 0; nj < 4; nj++) {
                    asm volatile(
                        "mma.sync.aligned.m16n8k8.row.col.f32.tf32.tf32.f32 "
                        "{%0,%1,%2,%3}, {%4,%5,%6,%7}, {%8,%9}, {%0,%1,%2,%3};\n"
                        : "+f"(c[mi][nj][0]), "+f"(c[mi][nj][1]),
                          "+f"(c[mi][nj][2]), "+f"(c[mi][nj][3])
                        : "r"(a[mi][0]), "r"(a[mi][1]), "r"(a[mi][2]), "r"(a[mi][3]),
                          "r"(b[nj][0]), "r"(b[nj][1]));
                }
        }
    }

    // ---- epilogue: fp16 h1 store + fused attention logits (pre-scaled by log2e)
#pragma unroll
    for (int mi = 0; mi < 2; mi++) {
        int r1 = row0 + m0 + mi * 16 + g;
        int r2 = r1 + 8;
#pragma unroll
        for (int nj = 0; nj < 4; nj++) {
            int hh = wn * 4 + nj;
            float w0 = attS[hh * 8 + 2 * tg], w1 = attS[hh * 8 + 2 * tg + 1];
            float u0 = attD[hh * 8 + 2 * tg], u1 = attD[hh * 8 + 2 * tg + 1];
            float s1 = c[mi][nj][0] * w0 + c[mi][nj][1] * w1;
            float d1v = c[mi][nj][0] * u0 + c[mi][nj][1] * u1;
            float s2 = c[mi][nj][2] * w0 + c[mi][nj][3] * w1;
            float d2v = c[mi][nj][2] * u0 + c[mi][nj][3] * u1;
#pragma unroll
            for (int o = 1; o <= 2; o <<= 1) {
                s1  += __shfl_xor_sync(0xFFFFFFFFu, s1,  o);
                d1v += __shfl_xor_sync(0xFFFFFFFFu, d1v, o);
                s2  += __shfl_xor_sync(0xFFFFFFFFu, s2,  o);
                d2v += __shfl_xor_sync(0xFFFFFFFFu, d2v, o);
            }
            int cp = (n0 + nj * 8) / 2 + tg;
            if (r1 < n) {
                ((__half2*)g_h1h)[r1 * 32 + cp] = __floats2half2_rn(c[mi][nj][0], c[mi][nj][1]);
                if (tg == 0) { g_as1[r1 * 8 + hh] = s1 * LOG2E; g_ad1[r1 * 8 + hh] = d1v * LOG2E; }
            }
            if (r2 < n) {
                ((__half2*)g_h1h)[r2 * 32 + cp] = __floats2half2_rn(c[mi][nj][2], c[mi][nj][3]);
                if (tg == 0) { g_as1[r2 * 8 + hh] = s2 * LOG2E; g_ad1[r2 * 8 + hh] = d2v * LOG2E; }
            }
        }
    }
}

// ---------------- layer-1 aggregate: 4 dsts/warp, lane=(dst,head), 8ch/lane --
__global__ void k_agg1(const float* __restrict__ b1, int n) {
    int gwarp = (blockIdx.x * blockDim.x + threadIdx.x) >> 5;
    int lane  = threadIdx.x & 31;
    int d0    = gwarp * 4;
    if (d0 >= n) return;                      // warp-uniform
    int slot = lane >> 3;                     // which dst (0..3)
    int h    = lane & 7;                      // head
    int d    = d0 + slot;
    bool valid = d < n;
    int dd = valid ? d : n - 1;
    float adv = g_ad1[dd * 8 + h];
    const uint4* h1p = (const uint4*)g_h1h;   // row = 8 uint4 (64 half); chunk h = head h

    float a0 = 0.f, a1 = 0.f, a2 = 0.f, a3 = 0.f;
    float a4 = 0.f, a5 = 0.f, a6 = 0.f, a7 = 0.f;
    float den = 0.f;
    int s0  = g_row[dd];
    int cnt = valid ? (g_row[dd + 1] - s0) : 0;
    int m = cnt;
    m = max(m, __shfl_xor_sync(0xFFFFFFFFu, m, 8));
    m = max(m, __shfl_xor_sync(0xFFFFFFFFu, m, 16));
    for (int k = 0; k < m; k++) {
        bool on = k < cnt;
        int s = on ? g_csr[s0 + k] : dd;
        float a = g_as1[s * 8 + h];
        uint4 hv = h1p[s * 8 + h];
        float w = on ? exp2f(lrelu(a + adv)) : 0.f;
        float2 f0 = __half22float2(*(const __half2*)&hv.x);
        float2 f1 = __half22float2(*(const __half2*)&hv.y);
        float2 f2 = __half22float2(*(const __half2*)&hv.z);
        float2 f3 = __half22float2(*(const __half2*)&hv.w);
        a0 += w * f0.x; a1 += w * f0.y;
        a2 += w * f1.x; a3 += w * f1.y;
        a4 += w * f2.x; a5 += w * f2.y;
        a6 += w * f3.x; a7 += w * f3.y;
        den += w;
    }
    {   // self loop
        float w = exp2f(lrelu(g_as1[dd * 8 + h] + adv));
        uint4 hv = h1p[dd * 8 + h];
        float2 f0 = __half22float2(*(const __half2*)&hv.x);
        float2 f1 = __half22float2(*(const __half2*)&hv.y);
        float2 f2 = __half22float2(*(const __half2*)&hv.z);
        float2 f3 = __half22float2(*(const __half2*)&hv.w);
        a0 += w * f0.x; a1 += w * f0.y;
        a2 += w * f1.x; a3 += w * f1.y;
        a4 += w * f2.x; a5 += w * f2.y;
        a6 += w * f3.x; a7 += w * f3.y;
        den += w;
    }
    if (!valid) return;
    float inv = 1.f / (den + 1e-16f);
    float4 blo = ((const float4*)b1)[h * 2];
    float4 bhi = ((const float4*)b1)[h * 2 + 1];
    float v0 = a0 * inv + blo.x, v1 = a1 * inv + blo.y;
    float v2 = a2 * inv + blo.z, v3 = a3 * inv + blo.w;
    float v4 = a4 * inv + bhi.x, v5 = a5 * inv + bhi.y;
    float v6 = a6 * inv + bhi.z, v7 = a7 * inv + bhi.w;
    v0 = v0 > 0.f ? v0 : expm1f(v0);  v1 = v1 > 0.f ? v1 : expm1f(v1);
    v2 = v2 > 0.f ? v2 : expm1f(v2);  v3 = v3 > 0.f ? v3 : expm1f(v3);
    v4 = v4 > 0.f ? v4 : expm1f(v4);  v5 = v5 > 0.f ? v5 : expm1f(v5);
    v6 = v6 > 0.f ? v6 : expm1f(v6);  v7 = v7 > 0.f ? v7 : expm1f(v7);
    __half2 p0 = __floats2half2_rn(v0, v1);
    __half2 p1 = __floats2half2_rn(v2, v3);
    __half2 p2 = __floats2half2_rn(v4, v5);
    __half2 p3 = __floats2half2_rn(v6, v7);
    uint4 o;
    o.x = *(const unsigned*)&p0; o.y = *(const unsigned*)&p1;
    o.z = *(const unsigned*)&p2; o.w = *(const unsigned*)&p3;
    ((uint4*)g_hacth)[d * 8 + h] = o;
}

// ---------------- GEMM2 + fused layer-2 logits -------------------------------
__global__ void k_gemm2(const float* __restrict__ W2,
                        const float* __restrict__ attS, const float* __restrict__ attD, int n) {
    __shared__ float Hs[64][65];
    __shared__ float Ws[64][NCLS];
    const int row0 = blockIdx.x * 64;
    const int t = threadIdx.x;

    for (int i = t; i < 64 * NCLS; i += 256) Ws[i / NCLS][i % NCLS] = W2[i];
#pragma unroll
    for (int i = 0; i < 8; i++) {
        int idx = t + i * 256;
        int r = idx >> 5, c2 = idx & 31;
        int row = row0 + r;
        float2 v = make_float2(0.f, 0.f);
        if (row < n) v = __half22float2(((const __half2*)g_hacth)[row * 32 + c2]);
        Hs[r][c2 * 2] = v.x;
        Hs[r][c2 * 2 + 1] = v.y;
    }
    __syncthreads();

    int r  = t >> 2;
    int c0 = (t & 3) * 10;
    float acc[10];
#pragma unroll
    for (int j = 0; j < 10; j++) acc[j] = 0.f;
#pragma unroll
    for (int k = 0; k < 64; k++) {
        float hv = Hs[r][k];
#pragma unroll
        for (int j = 0; j < 10; j++) acc[j] += hv * Ws[k][c0 + j];
    }

    float asp = 0.f, adp = 0.f;
#pragma unroll
    for (int j = 0; j < 10; j++) {
        asp += acc[j] * attS[c0 + j];
        adp += acc[j] * attD[c0 + j];
    }
#pragma unroll
    for (int o = 1; o <= 2; o <<= 1) {
        asp += __shfl_xor_sync(0xFFFFFFFFu, asp, o);
        adp += __shfl_xor_sync(0xFFFFFFFFu, adp, o);
    }

    int row = row0 + r;
    if (row < n) {
#pragma unroll
        for (int j = 0; j < 10; j += 2)
            ((__half2*)g_h2h)[row * 20 + (c0 + j) / 2] = __floats2half2_rn(acc[j], acc[j + 1]);
        if ((t & 3) == 0) { g_as2[row] = asp * LOG2E; g_ad2[row] = adp * LOG2E; }
    }
}

// ---------------- layer-2 aggregate+softmax: 4 dsts/warp, uint4 per lane -----
__global__ void k_agg2(const float* __restrict__ b2, float* __restrict__ out, int n) {
    int gwarp = (blockIdx.x * blockDim.x + threadIdx.x) >> 5;
    int lane  = threadIdx.x & 31;
    int d0    = gwarp * 4;
    if (d0 >= n) return;                      // warp-uniform
    int slot = lane >> 3;                     // which dst (0..3)
    int part = lane & 7;                      // channel chunk
    int d    = d0 + slot;
    bool valid = d < n;
    int dd = valid ? d : n - 1;
    bool act = part < 5;
    int cp = act ? part : 0;
    float adv = g_ad2[dd];
    const uint4* h2p = (const uint4*)g_h2h;   // row = 5 uint4

    float a0 = 0.f, a1 = 0.f, a2 = 0.f, a3 = 0.f;
    float a4 = 0.f, a5 = 0.f, a6 = 0.f, a7 = 0.f;
    float den = 0.f;
    int s0  = g_row[dd];
    int cnt = valid ? (g_row[dd + 1] - s0) : 0;
    int m = cnt;
    m = max(m, __shfl_xor_sync(0xFFFFFFFFu, m, 8));
    m = max(m, __shfl_xor_sync(0xFFFFFFFFu, m, 16));
    for (int k = 0; k < m; k++) {
        bool on = k < cnt;
        int s = on ? g_csr[s0 + k] : dd;
        float a = g_as2[s];
        uint4 hv = h2p[s * 5 + cp];
        float w = on ? exp2f(lrelu(a + adv)) : 0.f;
        float2 f0 = __half22float2(*(const __half2*)&hv.x);
        float2 f1 = __half22float2(*(const __half2*)&hv.y);
        float2 f2 = __half22float2(*(const __half2*)&hv.z);
        float2 f3 = __half22float2(*(const __half2*)&hv.w);
        a0 += w * f0.x; a1 += w * f0.y;
        a2 += w * f1.x; a3 += w * f1.y;
        a4 += w * f2.x; a5 += w * f2.y;
        a6 += w * f3.x; a7 += w * f3.y;
        den += w;
    }
    {   // self loop
        float w = exp2f(lrelu(g_as2[dd] + adv));
        uint4 hv = h2p[dd * 5 + cp];
        float2 f0 = __half22float2(*(const __half2*)&hv.x);
        float2 f1 = __half22float2(*(const __half2*)&hv.y);
        float2 f2 = __half22float2(*(const __half2*)&hv.z);
        float2 f3 = __half22float2(*(const __half2*)&hv.w);
        a0 += w * f0.x; a1 += w * f0.y;
        a2 += w * f1.x; a3 += w * f1.y;
        a4 += w * f2.x; a5 += w * f2.y;
        a6 += w * f3.x; a7 += w * f3.y;
        den += w;
    }
    float inv = 1.f / (den + 1e-16f);
    float v0 = -INFINITY, v1 = -INFINITY, v2 = -INFINITY, v3 = -INFINITY;
    float v4 = -INFINITY, v5 = -INFINITY, v6 = -INFINITY, v7 = -INFINITY;
    if (act) {
        float4 blo = ((const float4*)b2)[part * 2];
        float4 bhi = ((const float4*)b2)[part * 2 + 1];
        v0 = a0 * inv + blo.x; v1 = a1 * inv + blo.y;
        v2 = a2 * inv + blo.z; v3 = a3 * inv + blo.w;
        v4 = a4 * inv + bhi.x; v5 = a5 * inv + bhi.y;
        v6 = a6 * inv + bhi.z; v7 = a7 * inv + bhi.w;
    }
    // softmax over 40 values within the 8-lane dst group (xor 1,2,4)
    float mx = fmaxf(fmaxf(fmaxf(v0, v1), fmaxf(v2, v3)),
                     fmaxf(fmaxf(v4, v5), fmaxf(v6, v7)));
#pragma unroll
    for (int o = 4; o > 0; o >>= 1) mx = fmaxf(mx, __shfl_xor_sync(0xFFFFFFFFu, mx, o));
    float e0 = 0.f, e1 = 0.f, e2 = 0.f, e3 = 0.f, e4 = 0.f, e5 = 0.f, e6 = 0.f, e7 = 0.f;
    if (act) {
        e0 = expf(v0 - mx); e1 = expf(v1 - mx); e2 = expf(v2 - mx); e3 = expf(v3 - mx);
        e4 = expf(v4 - mx); e5 = expf(v5 - mx); e6 = expf(v6 - mx); e7 = expf(v7 - mx);
    }
    float ssum = e0 + e1 + e2 + e3 + e4 + e5 + e6 + e7;
#pragma unroll
    for (int o = 4; o > 0; o >>= 1) ssum += __shfl_xor_sync(0xFFFFFFFFu, ssum, o);
    float rr = 1.f / ssum;
    if (act && valid) {
        float* op = out + (size_t)d * NCLS + part * 8;
        ((float4*)op)[0] = make_float4(e0 * rr, e1 * rr, e2 * rr, e3 * rr);
        ((float4*)op)[1] = make_float4(e4 * rr, e5 * rr, e6 * rr, e7 * rr);
    }
}

// ---------------- launch ------------------------------------------------------
extern "C" void kernel_launch(void* const* d_in, const int* in_sizes, int n_in,
                              void* d_out, int out_size) {
    const float* x    = (const float*)d_in[0];
    const void*  ei   = d_in[1];
    const float* W1   = (const float*)d_in[2];
    const float* as1w = (const float*)d_in[3];
    const float* ad1w = (const float*)d_in[4];
    const float* b1   = (const float*)d_in[5];
    const float* W2   = (const float*)d_in[6];
    const float* as2w = (const float*)d_in[7];
    const float* ad2w = (const float*)d_in[8];
    const float* b2   = (const float*)d_in[9];
    float* out = (float*)d_out;

    int n = in_sizes[0] / FIN;       // 100000
    int E = in_sizes[1] / 2;         // 1600000
    int nb = (n + SCAN_B - 1) / SCAN_B;   // 98 (<= #SMs, all-resident for k_scan)

    const int gemm1_smem = GEMM1_SMEM_FLOATS * 4;   // 44544 bytes
    cudaFuncSetAttribute(k_gemm1_build, cudaFuncAttributeMaxDynamicSharedMemorySize, gemm1_smem);

    const int gemmBlocks = (n + 127) / 128;         // 782
    const int edgeBlocks = (E + 255) / 256;         // 6250
    const int aggWarps   = (n + 3) / 4;             // 4 dsts per warp
    const int aggBlocks  = (aggWarps * 32 + 255) / 256;

    // GEMM1 is CSR-independent: overlap the degree histogram with it.
    k_gemm1_build<<<gemmBlocks + edgeBlocks, 256, gemm1_smem>>>(x, W1, as1w, ad1w, ei, n, E, gemmBlocks); // 1
    k_scan   <<<nb, SCAN_B>>>(n, E);                                             // 2
    k_scatter<<<edgeBlocks, 256>>>(ei, E);                                       // 3
    k_agg1   <<<aggBlocks, 256>>>(b1, n);                                        // 4 <- profiled
    k_gemm2  <<<(n + 63) / 64, 256>>>(W2, as2w, ad2w, n);                        // 5
    k_agg2   <<<aggBlocks, 256>>>(b2, out, n);                                   // 6
}

// round 17
// speedup vs baseline: 1.0328x; 1.0328x over previous
#include <cuda_runtime.h>
#include <cuda_fp16.h>
#include <math.h>
#include <stdint.h>

#define NMAX  100000
#define EMAX  1600000
#define FIN   512
#define H1    8
#define D1    64      // H1 * C1
#define NCLS  40
#define SLOPE 0.2f
#define SCAN_B 1024
#define LOG2E 1.4426950408889634f

// dynamic smem for gemm1 part: As[2][128][36] then Bs[2][32][72]
#define GEMM1_SMEM_FLOATS (2*128*36 + 2*32*72)   // 13824 floats = 55296 B
#define AS_OFF 0
#define BS_OFF (2*128*36)

// ---------------- scratch (static device globals; no allocations) ----------
__device__ __align__(256) int    g_csr [EMAX];      // src ids grouped by dst
__device__ __align__(256) int    g_deg [NMAX];      // zero-init; re-zeroed by k_scan each run
__device__ __align__(256) int    g_row [NMAX + 1];  // CSR row pointers
__device__ __align__(256) int    g_cur [NMAX];
__device__ __align__(256) volatile long long g_bsum64[SCAN_B];  // flagged block sums
__device__ __align__(256) __half g_h1h [NMAX * D1];    // h1 in fp16 (gathered)
__device__ __align__(256) float  g_as1 [NMAX * H1];    // logits pre-scaled by log2(e)
__device__ __align__(256) float  g_ad1 [NMAX * H1];
__device__ __align__(256) __half g_hacth[NMAX * D1];   // hact in fp16
__device__ __align__(256) __half g_h2h [NMAX * NCLS];  // h2 in fp16 (gathered); row = 5 uint4
__device__ __align__(256) float  g_as2 [NMAX];         // pre-scaled by log2(e)
__device__ __align__(256) float  g_ad2 [NMAX];

// branch-free leaky-relu (slope>0): max(t, 0.2t)
__device__ __forceinline__ float lrelu(float v) { return fmaxf(v, SLOPE * v); }

// per-block int64-vs-int32 detection
__device__ __forceinline__ int detect_is64_block(const int* ei) {
    __shared__ int s_is64;
    if (threadIdx.x == 0) {
        int nz = 0;
#pragma unroll
        for (int k = 1; k < 32; k += 2) nz |= ei[k];
        s_is64 = (nz == 0);
    }
    __syncthreads();
    return s_is64;
}

// ---------------- single-kernel exclusive scan (all blocks co-resident) -----
__global__ void k_scan(int n, int E) {
    __shared__ int sh[SCAN_B];
    __shared__ int s_off;
    const int tid = threadIdx.x, bid = blockIdx.x;
    const int i = bid * SCAN_B + tid;
    int v = (i < n) ? g_deg[i] : 0;
    if (i < n) g_deg[i] = 0;                 // restore state for next replay
    sh[tid] = v;
    __syncthreads();
#pragma unroll
    for (int off = 1; off < SCAN_B; off <<= 1) {
        int t = (tid >= off) ? sh[tid - off] : 0;
        __syncthreads();
        sh[tid] += t;
        __syncthreads();
    }
    int incl = sh[tid];
    if (tid == SCAN_B - 1)
        g_bsum64[bid] = (1LL << 32) | (unsigned)incl;
    if (tid < 32) {
        int sum = 0;
        for (int p = tid; p < bid; p += 32) {
            long long w;
            do { w = g_bsum64[p]; } while ((int)(w >> 32) == 0);
            sum += (int)w;
        }
#pragma unroll
        for (int o = 16; o > 0; o >>= 1) sum += __shfl_xor_sync(0xFFFFFFFFu, sum, o);
        if (tid == 0) s_off = sum;
    }
    __syncthreads();
    if (i < n) {
        int r = s_off + incl - v;
        g_row[i] = r;
        g_cur[i] = r;
    }
    if (i == n - 1) g_row[n] = E;
}

// ---------------- vectorized scatter: 4 edges/thread (block 0 resets flags) -
__global__ void k_scatter(const void* __restrict__ ei, int E) {
    if (blockIdx.x == 0)
        for (int k = threadIdx.x; k < SCAN_B; k += 256)
            g_bsum64[k] = 0;
    int is64 = detect_is64_block((const int*)ei);
    int i4 = (blockIdx.x * 256 + threadIdx.x) * 4;
    if (i4 >= E) return;
    int s[4], d[4];
    int cnt = min(4, E - i4);
    if (cnt == 4) {
        if (is64) {
            const long long* p = (const long long*)ei;
            longlong2 s0 = *(const longlong2*)(p + i4);
            longlong2 s1 = *(const longlong2*)(p + i4 + 2);
            longlong2 d0 = *(const longlong2*)(p + (long long)E + i4);
            longlong2 d1 = *(const longlong2*)(p + (long long)E + i4 + 2);
            s[0] = (int)s0.x; s[1] = (int)s0.y; s[2] = (int)s1.x; s[3] = (int)s1.y;
            d[0] = (int)d0.x; d[1] = (int)d0.y; d[2] = (int)d1.x; d[3] = (int)d1.y;
        } else {
            const int* p = (const int*)ei;
            int4 sv = *(const int4*)(p + i4);
            int4 dv = *(const int4*)(p + E + i4);
            s[0] = sv.x; s[1] = sv.y; s[2] = sv.z; s[3] = sv.w;
            d[0] = dv.x; d[1] = dv.y; d[2] = dv.z; d[3] = dv.w;
        }
    } else {
        for (int k = 0; k < cnt; k++) {
            if (is64) {
                const long long* p = (const long long*)ei;
                s[k] = (int)p[i4 + k];
                d[k] = (int)p[(long long)E + i4 + k];
            } else {
                const int* p = (const int*)ei;
                s[k] = p[i4 + k];
                d[k] = p[E + i4 + k];
            }
        }
    }
#pragma unroll
    for (int k = 0; k < 4; k++) {
        if (k < cnt) {
            int pos = atomicAdd(&g_cur[d[k]], 1);
            g_csr[pos] = s[k];
        }
    }
}

// ---------------- fused: GEMM1 (TF32 mma, cp.async) + vectorized histogram --
// blocks [0, gemmBlocks): GEMM1 h1 = x @ W1 with fused attention logits
// blocks [gemmBlocks, ...): degree histogram, 4 edges/thread (overlaps GEMM)
__global__ __launch_bounds__(256, 3)
void k_gemm1_build(const float* __restrict__ x, const float* __restrict__ W,
                   const float* __restrict__ attS, const float* __restrict__ attD,
                   const void* __restrict__ ei, int n, int E, int gemmBlocks) {
    if ((int)blockIdx.x >= gemmBlocks) {
        // ------- histogram part: 4 dsts per thread -------
        int b = blockIdx.x - gemmBlocks;
        int is64 = detect_is64_block((const int*)ei);
        int i4 = (b * 256 + threadIdx.x) * 4;
        if (i4 >= E) return;
        int cnt = min(4, E - i4);
        int d[4];
        if (cnt == 4) {
            if (is64) {
                const long long* p = (const long long*)ei;
                longlong2 d0 = *(const longlong2*)(p + (long long)E + i4);
                longlong2 d1 = *(const longlong2*)(p + (long long)E + i4 + 2);
                d[0] = (int)d0.x; d[1] = (int)d0.y; d[2] = (int)d1.x; d[3] = (int)d1.y;
            } else {
                int4 dv = *(const int4*)((const int*)ei + E + i4);
                d[0] = dv.x; d[1] = dv.y; d[2] = dv.z; d[3] = dv.w;
            }
        } else {
            for (int k = 0; k < cnt; k++) {
                if (is64) d[k] = (int)((const long long*)ei)[(long long)E + i4 + k];
                else      d[k] = ((const int*)ei)[E + i4 + k];
            }
        }
#pragma unroll
        for (int k = 0; k < 4; k++)
            if (k < cnt) atomicAdd(&g_deg[d[k]], 1);
        return;
    }

    // ------- GEMM part: block tile M=128 N=64 K=32; 8 warps 4x2; mma m16n8k8
    extern __shared__ float sm[];
    float* Asm = sm + AS_OFF;
    float* Bsm = sm + BS_OFF;
    const int t    = threadIdx.x;
    const int warp = t >> 5, lane = t & 31;
    const int g    = lane >> 2, tg = lane & 3;
    const int wm   = warp >> 1, wn = warp & 1;
    const int m0   = wm * 32, n0 = wn * 32;
    const int row0 = blockIdx.x * 128;

    float c[2][4][4];
#pragma unroll
    for (int mi = 0; mi < 2; mi++)
#pragma unroll
        for (int nj = 0; nj < 4; nj++)
#pragma unroll
            for (int q = 0; q < 4; q++) c[mi][nj][q] = 0.f;

    auto load_stage = [&](int stage, int buf) {
        const int k0 = stage * 32;
        float* Ab = Asm + buf * 128 * 36;
        float* Bb = Bsm + buf * 32 * 72;
#pragma unroll
        for (int p = 0; p < 4; p++) {
            int idx = t + p * 256;
            int r = idx >> 3, c4 = idx & 7;
            const float* src = x + (size_t)(row0 + r) * FIN + k0 + c4 * 4;
            uint32_t daddr = (uint32_t)__cvta_generic_to_shared(Ab + r * 36 + c4 * 4);
            int sb = (row0 + r < n) ? 16 : 0;
            asm volatile("cp.async.cg.shared.global [%0], [%1], 16, %2;\n"
                         :: "r"(daddr), "l"(src), "r"(sb));
        }
#pragma unroll
        for (int p = 0; p < 2; p++) {
            int idx = t + p * 256;
            int kk = idx >> 4, n4 = idx & 15;
            const float* src = W + (size_t)(k0 + kk) * D1 + n4 * 4;
            uint32_t daddr = (uint32_t)__cvta_generic_to_shared(Bb + kk * 72 + n4 * 4);
            asm volatile("cp.async.cg.shared.global [%0], [%1], 16;\n"
                         :: "r"(daddr), "l"(src));
        }
    };

    load_stage(0, 0);
    asm volatile("cp.async.commit_group;\n");

    const int NSTAGE = FIN / 32;   // 16
    for (int it = 0; it < NSTAGE; it++) {
        if (it + 1 < NSTAGE) {
            load_stage(it + 1, (it + 1) & 1);
            asm volatile("cp.async.commit_group;\n");
            asm volatile("cp.async.wait_group 1;\n");
        } else {
            asm volatile("cp.async.wait_group 0;\n");
        }
        __syncthreads();
        const int buf = it & 1;
        const float* Ab = Asm + buf * 128 * 36;
        const float* Bb = Bsm + buf * 32 * 72;
#pragma unroll
        for (int ks = 0; ks < 4; ks++) {
            const int kb = ks * 8;
            uint32_t a[2][4], b[4][2];
#pragma unroll
            for (int mi = 0; mi < 2; mi++) {
                const int mr = m0 + mi * 16;
                a[mi][0] = __float_as_uint(Ab[(mr + g    ) * 36 + kb + tg    ]);
                a[mi][1] = __float_as_uint(Ab[(mr + g + 8) * 36 + kb + tg    ]);
                a[mi][2] = __float_as_uint(Ab[(mr + g    ) * 36 + kb + tg + 4]);
                a[mi][3] = __float_as_uint(Ab[(mr + g + 8) * 36 + kb + tg + 4]);
            }
#pragma unroll
            for (int nj = 0; nj < 4; nj++) {
                const int nc = n0 + nj * 8;
                b[nj][0] = __float_as_uint(Bb[(kb + tg    ) * 72 + nc + g]);
                b[nj][1] = __float_as_uint(Bb[(kb + tg + 4) * 72 + nc + g]);
            }
#pragma unroll
            for (int mi = 0; mi < 2; mi++)
#pragma unroll
                for (int nj = 0; nj < 4; nj++) {
                    asm volatile(
                        "mma.sync.aligned.m16n8k8.row.col.f32.tf32.tf32.f32 "
                        "{%0,%1,%2,%3}, {%4,%5,%6,%7}, {%8,%9}, {%0,%1,%2,%3};\n"
                        : "+f"(c[mi][nj][0]), "+f"(c[mi][nj][1]),
                          "+f"(c[mi][nj][2]), "+f"(c[mi][nj][3])
                        : "r"(a[mi][0]), "r"(a[mi][1]), "r"(a[mi][2]), "r"(a[mi][3]),
                          "r"(b[nj][0]), "r"(b[nj][1]));
                }
        }
        __syncthreads();
    }

    // ---- epilogue: fp16 h1 store + fused attention logits (pre-scaled by log2e)
#pragma unroll
    for (int mi = 0; mi < 2; mi++) {
        int r1 = row0 + m0 + mi * 16 + g;
        int r2 = r1 + 8;
#pragma unroll
        for (int nj = 0; nj < 4; nj++) {
            int hh = wn * 4 + nj;
            float w0 = attS[hh * 8 + 2 * tg], w1 = attS[hh * 8 + 2 * tg + 1];
            float u0 = attD[hh * 8 + 2 * tg], u1 = attD[hh * 8 + 2 * tg + 1];
            float s1 = c[mi][nj][0] * w0 + c[mi][nj][1] * w1;
            float d1v = c[mi][nj][0] * u0 + c[mi][nj][1] * u1;
            float s2 = c[mi][nj][2] * w0 + c[mi][nj][3] * w1;
            float d2v = c[mi][nj][2] * u0 + c[mi][nj][3] * u1;
#pragma unroll
            for (int o = 1; o <= 2; o <<= 1) {
                s1  += __shfl_xor_sync(0xFFFFFFFFu, s1,  o);
                d1v += __shfl_xor_sync(0xFFFFFFFFu, d1v, o);
                s2  += __shfl_xor_sync(0xFFFFFFFFu, s2,  o);
                d2v += __shfl_xor_sync(0xFFFFFFFFu, d2v, o);
            }
            int cp = (n0 + nj * 8) / 2 + tg;
            if (r1 < n) {
                ((__half2*)g_h1h)[r1 * 32 + cp] = __floats2half2_rn(c[mi][nj][0], c[mi][nj][1]);
                if (tg == 0) { g_as1[r1 * 8 + hh] = s1 * LOG2E; g_ad1[r1 * 8 + hh] = d1v * LOG2E; }
            }
            if (r2 < n) {
                ((__half2*)g_h1h)[r2 * 32 + cp] = __floats2half2_rn(c[mi][nj][2], c[mi][nj][3]);
                if (tg == 0) { g_as1[r2 * 8 + hh] = s2 * LOG2E; g_ad1[r2 * 8 + hh] = d2v * LOG2E; }
            }
        }
    }
}

// ---------------- layer-1 aggregate: 4 dsts/warp, lane=(dst,head), 8ch/lane --
__global__ void k_agg1(const float* __restrict__ b1, int n) {
    int gwarp = (blockIdx.x * blockDim.x + threadIdx.x) >> 5;
    int lane  = threadIdx.x & 31;
    int d0    = gwarp * 4;
    if (d0 >= n) return;                      // warp-uniform
    int slot = lane >> 3;                     // which dst (0..3)
    int h    = lane & 7;                      // head
    int d    = d0 + slot;
    bool valid = d < n;
    int dd = valid ? d : n - 1;
    float adv = g_ad1[dd * 8 + h];
    const uint4* h1p = (const uint4*)g_h1h;   // row = 8 uint4 (64 half); chunk h = head h

    float a0 = 0.f, a1 = 0.f, a2 = 0.f, a3 = 0.f;
    float a4 = 0.f, a5 = 0.f, a6 = 0.f, a7 = 0.f;
    float den = 0.f;
    int s0  = g_row[dd];
    int cnt = valid ? (g_row[dd + 1] - s0) : 0;
    int m = cnt;
    m = max(m, __shfl_xor_sync(0xFFFFFFFFu, m, 8));
    m = max(m, __shfl_xor_sync(0xFFFFFFFFu, m, 16));
    for (int k = 0; k < m; k++) {
        bool on = k < cnt;
        int s = on ? g_csr[s0 + k] : dd;
        float a = g_as1[s * 8 + h];
        uint4 hv = h1p[s * 8 + h];
        float w = on ? exp2f(lrelu(a + adv)) : 0.f;
        float2 f0 = __half22float2(*(const __half2*)&hv.x);
        float2 f1 = __half22float2(*(const __half2*)&hv.y);
        float2 f2 = __half22float2(*(const __half2*)&hv.z);
        float2 f3 = __half22float2(*(const __half2*)&hv.w);
        a0 += w * f0.x; a1 += w * f0.y;
        a2 += w * f1.x; a3 += w * f1.y;
        a4 += w * f2.x; a5 += w * f2.y;
        a6 += w * f3.x; a7 += w * f3.y;
        den += w;
    }
    {   // self loop
        float w = exp2f(lrelu(g_as1[dd * 8 + h] + adv));
        uint4 hv = h1p[dd * 8 + h];
        float2 f0 = __half22float2(*(const __half2*)&hv.x);
        float2 f1 = __half22float2(*(const __half2*)&hv.y);
        float2 f2 = __half22float2(*(const __half2*)&hv.z);
        float2 f3 = __half22float2(*(const __half2*)&hv.w);
        a0 += w * f0.x; a1 += w * f0.y;
        a2 += w * f1.x; a3 += w * f1.y;
        a4 += w * f2.x; a5 += w * f2.y;
        a6 += w * f3.x; a7 += w * f3.y;
        den += w;
    }
    if (!valid) return;
    float inv = 1.f / (den + 1e-16f);
    float4 blo = ((const float4*)b1)[h * 2];
    float4 bhi = ((const float4*)b1)[h * 2 + 1];
    float v0 = a0 * inv + blo.x, v1 = a1 * inv + blo.y;
    float v2 = a2 * inv + blo.z, v3 = a3 * inv + blo.w;
    float v4 = a4 * inv + bhi.x, v5 = a5 * inv + bhi.y;
    float v6 = a6 * inv + bhi.z, v7 = a7 * inv + bhi.w;
    v0 = v0 > 0.f ? v0 : expm1f(v0);  v1 = v1 > 0.f ? v1 : expm1f(v1);
    v2 = v2 > 0.f ? v2 : expm1f(v2);  v3 = v3 > 0.f ? v3 : expm1f(v3);
    v4 = v4 > 0.f ? v4 : expm1f(v4);  v5 = v5 > 0.f ? v5 : expm1f(v5);
    v6 = v6 > 0.f ? v6 : expm1f(v6);  v7 = v7 > 0.f ? v7 : expm1f(v7);
    __half2 p0 = __floats2half2_rn(v0, v1);
    __half2 p1 = __floats2half2_rn(v2, v3);
    __half2 p2 = __floats2half2_rn(v4, v5);
    __half2 p3 = __floats2half2_rn(v6, v7);
    uint4 o;
    o.x = *(const unsigned*)&p0; o.y = *(const unsigned*)&p1;
    o.z = *(const unsigned*)&p2; o.w = *(const unsigned*)&p3;
    ((uint4*)g_hacth)[d * 8 + h] = o;
}

// ---------------- GEMM2 + fused layer-2 logits -------------------------------
__global__ void k_gemm2(const float* __restrict__ W2,
                        const float* __restrict__ attS, const float* __restrict__ attD, int n) {
    __shared__ float Hs[64][65];
    __shared__ float Ws[64][NCLS];
    const int row0 = blockIdx.x * 64;
    const int t = threadIdx.x;

    for (int i = t; i < 64 * NCLS; i += 256) Ws[i / NCLS][i % NCLS] = W2[i];
#pragma unroll
    for (int i = 0; i < 8; i++) {
        int idx = t + i * 256;
        int r = idx >> 5, c2 = idx & 31;
        int row = row0 + r;
        float2 v = make_float2(0.f, 0.f);
        if (row < n) v = __half22float2(((const __half2*)g_hacth)[row * 32 + c2]);
        Hs[r][c2 * 2] = v.x;
        Hs[r][c2 * 2 + 1] = v.y;
    }
    __syncthreads();

    int r  = t >> 2;
    int c0 = (t & 3) * 10;
    float acc[10];
#pragma unroll
    for (int j = 0; j < 10; j++) acc[j] = 0.f;
#pragma unroll
    for (int k = 0; k < 64; k++) {
        float hv = Hs[r][k];
#pragma unroll
        for (int j = 0; j < 10; j++) acc[j] += hv * Ws[k][c0 + j];
    }

    float asp = 0.f, adp = 0.f;
#pragma unroll
    for (int j = 0; j < 10; j++) {
        asp += acc[j] * attS[c0 + j];
        adp += acc[j] * attD[c0 + j];
    }
#pragma unroll
    for (int o = 1; o <= 2; o <<= 1) {
        asp += __shfl_xor_sync(0xFFFFFFFFu, asp, o);
        adp += __shfl_xor_sync(0xFFFFFFFFu, adp, o);
    }

    int row = row0 + r;
    if (row < n) {
#pragma unroll
        for (int j = 0; j < 10; j += 2)
            ((__half2*)g_h2h)[row * 20 + (c0 + j) / 2] = __floats2half2_rn(acc[j], acc[j + 1]);
        if ((t & 3) == 0) { g_as2[row] = asp * LOG2E; g_ad2[row] = adp * LOG2E; }
    }
}

// ---------------- layer-2 aggregate+softmax: 4 dsts/warp, uint4 per lane -----
__global__ void k_agg2(const float* __restrict__ b2, float* __restrict__ out, int n) {
    int gwarp = (blockIdx.x * blockDim.x + threadIdx.x) >> 5;
    int lane  = threadIdx.x & 31;
    int d0    = gwarp * 4;
    if (d0 >= n) return;                      // warp-uniform
    int slot = lane >> 3;                     // which dst (0..3)
    int part = lane & 7;                      // channel chunk
    int d    = d0 + slot;
    bool valid = d < n;
    int dd = valid ? d : n - 1;
    bool act = part < 5;
    int cp = act ? part : 0;
    float adv = g_ad2[dd];
    const uint4* h2p = (const uint4*)g_h2h;   // row = 5 uint4

    float a0 = 0.f, a1 = 0.f, a2 = 0.f, a3 = 0.f;
    float a4 = 0.f, a5 = 0.f, a6 = 0.f, a7 = 0.f;
    float den = 0.f;
    int s0  = g_row[dd];
    int cnt = valid ? (g_row[dd + 1] - s0) : 0;
    int m = cnt;
    m = max(m, __shfl_xor_sync(0xFFFFFFFFu, m, 8));
    m = max(m, __shfl_xor_sync(0xFFFFFFFFu, m, 16));
    for (int k = 0; k < m; k++) {
        bool on = k < cnt;
        int s = on ? g_csr[s0 + k] : dd;
        float a = g_as2[s];
        uint4 hv = h2p[s * 5 + cp];
        float w = on ? exp2f(lrelu(a + adv)) : 0.f;
        float2 f0 = __half22float2(*(const __half2*)&hv.x);
        float2 f1 = __half22float2(*(const __half2*)&hv.y);
        float2 f2 = __half22float2(*(const __half2*)&hv.z);
        float2 f3 = __half22float2(*(const __half2*)&hv.w);
        a0 += w * f0.x; a1 += w * f0.y;
        a2 += w * f1.x; a3 += w * f1.y;
        a4 += w * f2.x; a5 += w * f2.y;
        a6 += w * f3.x; a7 += w * f3.y;
        den += w;
    }
    {   // self loop
        float w = exp2f(lrelu(g_as2[dd] + adv));
        uint4 hv = h2p[dd * 5 + cp];
        float2 f0 = __half22float2(*(const __half2*)&hv.x);
        float2 f1 = __half22float2(*(const __half2*)&hv.y);
        float2 f2 = __half22float2(*(const __half2*)&hv.z);
        float2 f3 = __half22float2(*(const __half2*)&hv.w);
        a0 += w * f0.x; a1 += w * f0.y;
        a2 += w * f1.x; a3 += w * f1.y;
        a4 += w * f2.x; a5 += w * f2.y;
        a6 += w * f3.x; a7 += w * f3.y;
        den += w;
    }
    float inv = 1.f / (den + 1e-16f);
    float v0 = -INFINITY, v1 = -INFINITY, v2 = -INFINITY, v3 = -INFINITY;
    float v4 = -INFINITY, v5 = -INFINITY, v6 = -INFINITY, v7 = -INFINITY;
    if (act) {
        float4 blo = ((const float4*)b2)[part * 2];
        float4 bhi = ((const float4*)b2)[part * 2 + 1];
        v0 = a0 * inv + blo.x; v1 = a1 * inv + blo.y;
        v2 = a2 * inv + blo.z; v3 = a3 * inv + blo.w;
        v4 = a4 * inv + bhi.x; v5 = a5 * inv + bhi.y;
        v6 = a6 * inv + bhi.z; v7 = a7 * inv + bhi.w;
    }
    // softmax over 40 values within the 8-lane dst group (xor 1,2,4)
    float mx = fmaxf(fmaxf(fmaxf(v0, v1), fmaxf(v2, v3)),
                     fmaxf(fmaxf(v4, v5), fmaxf(v6, v7)));
#pragma unroll
    for (int o = 4; o > 0; o >>= 1) mx = fmaxf(mx, __shfl_xor_sync(0xFFFFFFFFu, mx, o));
    float e0 = 0.f, e1 = 0.f, e2 = 0.f, e3 = 0.f, e4 = 0.f, e5 = 0.f, e6 = 0.f, e7 = 0.f;
    if (act) {
        e0 = expf(v0 - mx); e1 = expf(v1 - mx); e2 = expf(v2 - mx); e3 = expf(v3 - mx);
        e4 = expf(v4 - mx); e5 = expf(v5 - mx); e6 = expf(v6 - mx); e7 = expf(v7 - mx);
    }
    float ssum = e0 + e1 + e2 + e3 + e4 + e5 + e6 + e7;
#pragma unroll
    for (int o = 4; o > 0; o >>= 1) ssum += __shfl_xor_sync(0xFFFFFFFFu, ssum, o);
    float rr = 1.f / ssum;
    if (act && valid) {
        float* op = out + (size_t)d * NCLS + part * 8;
        ((float4*)op)[0] = make_float4(e0 * rr, e1 * rr, e2 * rr, e3 * rr);
        ((float4*)op)[1] = make_float4(e4 * rr, e5 * rr, e6 * rr, e7 * rr);
    }
}

// ---------------- launch ------------------------------------------------------
extern "C" void kernel_launch(void* const* d_in, const int* in_sizes, int n_in,
                              void* d_out, int out_size) {
    const float* x    = (const float*)d_in[0];
    const void*  ei   = d_in[1];
    const float* W1   = (const float*)d_in[2];
    const float* as1w = (const float*)d_in[3];
    const float* ad1w = (const float*)d_in[4];
    const float* b1   = (const float*)d_in[5];
    const float* W2   = (const float*)d_in[6];
    const float* as2w = (const float*)d_in[7];
    const float* ad2w = (const float*)d_in[8];
    const float* b2   = (const float*)d_in[9];
    float* out = (float*)d_out;

    int n = in_sizes[0] / FIN;       // 100000
    int E = in_sizes[1] / 2;         // 1600000
    int nb = (n + SCAN_B - 1) / SCAN_B;   // 98 (<= #SMs, all-resident for k_scan)

    const int gemm1_smem = GEMM1_SMEM_FLOATS * 4;   // 55296 bytes
    cudaFuncSetAttribute(k_gemm1_build, cudaFuncAttributeMaxDynamicSharedMemorySize, gemm1_smem);

    const int gemmBlocks  = (n + 127) / 128;        // 782
    const int edgeBlocks4 = (E + 1023) / 1024;      // 1563 (4 edges/thread)
    const int aggWarps    = (n + 3) / 4;            // 4 dsts per warp
    const int aggBlocks   = (aggWarps * 32 + 127) / 128;   // 128-thread blocks

    // GEMM1 is CSR-independent: overlap the (vectorized) degree histogram with it.
    k_gemm1_build<<<gemmBlocks + edgeBlocks4, 256, gemm1_smem>>>(x, W1, as1w, ad1w, ei, n, E, gemmBlocks); // 1
    k_scan   <<<nb, SCAN_B>>>(n, E);                                             // 2
    k_scatter<<<edgeBlocks4, 256>>>(ei, E);                                      // 3
    k_agg1   <<<aggBlocks, 128>>>(b1, n);                                        // 4 <- profiled
    k_gemm2  <<<(n + 63) / 64, 256>>>(W2, as2w, ad2w, n);                        // 5
    k_agg2   <<<aggBlocks, 128>>>(b2, out, n);                                   // 6
}